// round 16
// baseline (speedup 1.0000x reference)
#include <cuda_runtime.h>
#include <cuda_fp16.h>
#include <cuda_fp8.h>
#include <cstdint>
#include <cstddef>

#define NMAX 50048
#define EMAX 1700000
#define FDIM 128
#define GNUM 64
#define HID2 64
#define OUTD 10

// ---------------- scratch ----------------
__device__ __align__(16) unsigned char  g_hw8 [NMAX * FDIM];  // h rows, e4m3 (scaled)
__device__ __align__(16) float g_acc[NMAX * FDIM];
__device__ __align__(16) float g_als[NMAX * 4];
__device__ __align__(16) float g_ald[NMAX * 4];
__device__ __align__(16) float g_colsum1[GNUM * FDIM];
__device__ __align__(16) float g_colsum2[GNUM * FDIM];
__device__ __align__(16) float g_num1[GNUM * FDIM];
__device__ __align__(16) float g_num2[GNUM * FDIM];
__device__ __align__(16) float g_gatesum1[GNUM];
__device__ __align__(16) float g_gatesum2[GNUM];
__device__ int g_src32[EMAX];
__device__ int g_dst32[EMAX];
__device__ int g_deg[NMAX];
__device__ int g_off[NMAX + 1];
__device__ int g_cur[NMAX];
__device__ int g_csr[EMAX];
__device__ int g_bsum[64];
__device__ int g_idx64;

__device__ __forceinline__ int load_idx(const void* p, long long i, int f64) {
    return f64 ? (int)((const long long*)p)[i] : ((const int*)p)[i];
}
__device__ __forceinline__ void red_add_v4(float* ptr, float a, float b, float c, float d) {
    asm volatile("red.global.add.v4.f32 [%0], {%1,%2,%3,%4};"
                 :: "l"(ptr), "f"(a), "f"(b), "f"(c), "f"(d) : "memory");
}
// fp8 row loader: lane covers features [4*lane, 4*lane+4)
__device__ __forceinline__ float4 ldrow8(int n, int lane) {
    unsigned int raw = ((const unsigned int*)(g_hw8 + (size_t)n * 128))[lane];
    __nv_fp8x2_storage_t lo = (__nv_fp8x2_storage_t)(raw & 0xffffu);
    __nv_fp8x2_storage_t hi = (__nv_fp8x2_storage_t)(raw >> 16);
    __half2_raw h0 = __nv_cvt_fp8x2_to_halfraw2(lo, __NV_E4M3);
    __half2_raw h1 = __nv_cvt_fp8x2_to_halfraw2(hi, __NV_E4M3);
    float2 f0 = __half22float2(*reinterpret_cast<__half2*>(&h0));
    float2 f1 = __half22float2(*reinterpret_cast<__half2*>(&h1));
    return make_float4(f0.x, f0.y, f1.x, f1.y);
}

// zero + index-width probe (merged)
__global__ void k_zero_pre(const void* ei, int N) {
    int t = blockIdx.x * blockDim.x + threadIdx.x;
    if (t == 0) {
        const int* w = (const int*)ei;
        int f = 1;
        for (int i = 0; i < 64; i++) if (w[2 * i + 1] != 0) { f = 0; break; }
        g_idx64 = f;
    }
    if (t < N) g_deg[t] = 0;
    if (t < GNUM * FDIM) {
        g_colsum1[t] = 0.f; g_colsum2[t] = 0.f;
        g_num1[t] = 0.f;    g_num2[t] = 0.f;
    }
    if (t < GNUM) { g_gatesum1[t] = 0.f; g_gatesum2[t] = 0.f; }
}

__global__ void k_prep(const void* __restrict__ ei, long long E) {
    long long t = (long long)blockIdx.x * blockDim.x + threadIdx.x;
    if (t >= E) return;
    int f64 = g_idx64;
    int s = load_idx(ei, t, f64);
    int d = load_idx(ei, E + t, f64);
    g_src32[t] = s;
    g_dst32[t] = d;
    atomicAdd(&g_deg[d], 1);
}

// ---- multi-block exclusive scan ----
__global__ void k_scan1(int N) {
    __shared__ int wsum[32];
    int b = blockIdx.x;
    int i = b * 1024 + threadIdx.x;
    int lane = threadIdx.x & 31, w = threadIdx.x >> 5;
    int v = (i < N) ? g_deg[i] : 0;
    int x = v;
#pragma unroll
    for (int off = 1; off < 32; off <<= 1) {
        int y = __shfl_up_sync(0xffffffffu, x, off);
        if (lane >= off) x += y;
    }
    if (lane == 31) wsum[w] = x;
    __syncthreads();
    if (w == 0) {
        int s = wsum[lane];
#pragma unroll
        for (int off = 1; off < 32; off <<= 1) {
            int y = __shfl_up_sync(0xffffffffu, s, off);
            if (lane >= off) s += y;
        }
        wsum[lane] = s;
    }
    __syncthreads();
    int excl = x - v + (w ? wsum[w - 1] : 0);
    if (i < N) g_off[i] = excl;
    if (threadIdx.x == 1023) g_bsum[b] = excl + v;
}

__global__ void k_scan3(int nb, int N) {
    __shared__ int s_off, s_tot;
    if (threadIdx.x < 32) {
        int lane = threadIdx.x;
        int v0 = (lane < nb) ? g_bsum[lane] : 0;
        int v1 = (lane + 32 < nb) ? g_bsum[lane + 32] : 0;
        int pre = 0, tot = 0;
        for (int j = 0; j < 64; j++) {
            int vj = __shfl_sync(0xffffffffu, (j < 32) ? v0 : v1, j & 31);
            if (j < (int)blockIdx.x) pre += vj;
            tot += vj;
        }
        if (lane == 0) { s_off = pre; s_tot = tot; }
    }
    __syncthreads();
    int i = blockIdx.x * 1024 + threadIdx.x;
    if (i < N) {
        int o = g_off[i] + s_off;
        g_off[i] = o;
        g_cur[i] = o;
    }
    if (blockIdx.x == 0 && threadIdx.x == 0) g_off[N] = s_tot;
}

__global__ void k_fill(long long E) {
    long long t = (long long)blockIdx.x * blockDim.x + threadIdx.x;
    if (t >= E) return;
    int s = g_src32[t];
    int d = g_dst32[t];
    int pos = atomicAdd(&g_cur[d], 1);
    g_csr[pos] = s;
}

// ---------------- register-tiled GEMM core ----------------
__device__ __forceinline__ void gemm_core(const float* sx, const float* sw,
                                          const float* __restrict__ a_src,
                                          const float* __restrict__ a_dst,
                                          int row0, int N, float scale) {
    int tx = threadIdx.x;
    int cg = tx & 15;
    int rg = tx >> 4;
    int r0 = rg * 8;
    unsigned long long acc2[8][4];
#pragma unroll
    for (int r = 0; r < 8; r++)
#pragma unroll
        for (int j = 0; j < 4; j++) acc2[r][j] = 0ull;

    for (int k = 0; k < 128; k += 4) {
        unsigned long long w0[4], w1[4], w2[4], w3[4];
#pragma unroll
        for (int j = 0; j < 4; j++) {
            w0[j] = *(const unsigned long long*)&sw[(k + 0) * 128 + j * 32 + cg * 2];
            w1[j] = *(const unsigned long long*)&sw[(k + 1) * 128 + j * 32 + cg * 2];
            w2[j] = *(const unsigned long long*)&sw[(k + 2) * 128 + j * 32 + cg * 2];
            w3[j] = *(const unsigned long long*)&sw[(k + 3) * 128 + j * 32 + cg * 2];
        }
#pragma unroll
        for (int r = 0; r < 8; r++) {
            float4 a = *(const float4*)&sx[(r0 + r) * 128 + k];
            unsigned long long da0, da1, da2, da3;
            asm("mov.b64 %0,{%1,%1};" : "=l"(da0) : "f"(a.x));
            asm("mov.b64 %0,{%1,%1};" : "=l"(da1) : "f"(a.y));
            asm("mov.b64 %0,{%1,%1};" : "=l"(da2) : "f"(a.z));
            asm("mov.b64 %0,{%1,%1};" : "=l"(da3) : "f"(a.w));
#pragma unroll
            for (int j = 0; j < 4; j++) {
                asm("fma.rn.f32x2 %0,%1,%2,%0;" : "+l"(acc2[r][j]) : "l"(da0), "l"(w0[j]));
                asm("fma.rn.f32x2 %0,%1,%2,%0;" : "+l"(acc2[r][j]) : "l"(da1), "l"(w1[j]));
                asm("fma.rn.f32x2 %0,%1,%2,%0;" : "+l"(acc2[r][j]) : "l"(da2), "l"(w2[j]));
                asm("fma.rn.f32x2 %0,%1,%2,%0;" : "+l"(acc2[r][j]) : "l"(da3), "l"(w3[j]));
            }
        }
    }
    float as_[8], ad_[8];
#pragma unroll
    for (int j = 0; j < 4; j++) {
        float2 s2 = *(const float2*)&a_src[j * 32 + cg * 2];
        float2 d2 = *(const float2*)&a_dst[j * 32 + cg * 2];
        as_[2 * j] = s2.x; as_[2 * j + 1] = s2.y;
        ad_[2 * j] = d2.x; ad_[2 * j + 1] = d2.y;
    }
#pragma unroll
    for (int r = 0; r < 8; r++) {
        int row = row0 + r0 + r;
        float e[8];
#pragma unroll
        for (int j = 0; j < 4; j++) {
            float lo, hi;
            asm("mov.b64 {%0,%1},%2;" : "=f"(lo), "=f"(hi) : "l"(acc2[r][j]));
            e[2 * j] = lo; e[2 * j + 1] = hi;
        }
        float ps[4], pd[4];
#pragma unroll
        for (int j = 0; j < 4; j++) {
            ps[j] = e[2 * j] * as_[2 * j] + e[2 * j + 1] * as_[2 * j + 1];
            pd[j] = e[2 * j] * ad_[2 * j] + e[2 * j + 1] * ad_[2 * j + 1];
        }
#pragma unroll
        for (int m = 1; m < 16; m <<= 1) {
#pragma unroll
            for (int j = 0; j < 4; j++) {
                ps[j] += __shfl_xor_sync(0xffffffffu, ps[j], m);
                pd[j] += __shfl_xor_sync(0xffffffffu, pd[j], m);
            }
        }
        if (row < N) {
#pragma unroll
            for (int j = 0; j < 4; j++) {
                unsigned short b0 = __nv_cvt_float_to_fp8(e[2 * j] * scale, __NV_SATFINITE, __NV_E4M3);
                unsigned short b1 = __nv_cvt_float_to_fp8(e[2 * j + 1] * scale, __NV_SATFINITE, __NV_E4M3);
                *(unsigned short*)&g_hw8[(size_t)row * 128 + j * 32 + cg * 2] =
                    (unsigned short)(b0 | (b1 << 8));
            }
            if (cg == 0) {
                *(float4*)&g_als[row * 4] = make_float4(ps[0], ps[1], ps[2], ps[3]);
                *(float4*)&g_ald[row * 4] = make_float4(pd[0], pd[1], pd[2], pd[3]);
            }
        }
    }
}

// ---------------- layer-1 GEMM (input x) ----------------
__global__ void __launch_bounds__(256, 1)
k_gemm(const float* __restrict__ A, const float* __restrict__ W,
       const float* __restrict__ a_src, const float* __restrict__ a_dst,
       int N, float scale) {
    extern __shared__ float smem[];
    float* sx = smem;
    float* sw = smem + 16384;
    int tx = threadIdx.x;
    int row0 = blockIdx.x * 128;
    float4* sx4 = (float4*)sx;
    float4* sw4 = (float4*)sw;
    const float4* A4 = (const float4*)A;
    const float4* W4 = (const float4*)W;
#pragma unroll
    for (int i = tx; i < 4096; i += 256) {
        int r = i >> 5;
        sx4[i] = (row0 + r < N) ? A4[(size_t)(row0 + r) * 32 + (i & 31)]
                                : make_float4(0.f, 0.f, 0.f, 0.f);
        sw4[i] = W4[i];
    }
    __syncthreads();
    gemm_core(sx, sw, a_src, a_dst, row0, N, scale);
}

// ---------------- fused: layer-1 ngp (softmax+gate+pool) + layer-2 GEMM -------
__global__ void __launch_bounds__(256, 1)
k_ngp_gemm(const void* __restrict__ batch, const float* __restrict__ gate_w,
           const float* __restrict__ gate_b, const float* __restrict__ W,
           const float* __restrict__ a_src, const float* __restrict__ a_dst,
           int N, float scale) {
    extern __shared__ float smem[];
    float* sx = smem;
    float* sw = smem + 16384;
    float* sge = smem + 32768;
    int* sgid = (int*)(smem + 32896);
    int tx = threadIdx.x;
    int lane = tx & 31;
    int row0 = blockIdx.x * 128;
    int f64 = g_idx64;
    float4* sx4 = (float4*)sx;
    float4* sw4 = (float4*)sw;
    const float4* W4 = (const float4*)W;
    const float4* acc4 = (const float4*)g_acc;
#pragma unroll
    for (int i = tx; i < 4096; i += 256) {
        int r = i >> 5, c = i & 31;
        int row = row0 + r;
        if (row < N) {
            int g = load_idx(batch, row, f64);
            if (c == 0) sgid[r] = g;
            float4 e = acc4[(size_t)row * 32 + c];
            float4 cs = ((const float4*)(g_colsum1 + g * 128))[c];
            sx4[i] = make_float4(__fdividef(e.x, cs.x), __fdividef(e.y, cs.y),
                                 __fdividef(e.z, cs.z), __fdividef(e.w, cs.w));
        } else {
            if (c == 0) sgid[r] = 0;
            sx4[i] = make_float4(0.f, 0.f, 0.f, 0.f);
        }
        sw4[i] = W4[i];
    }
    __syncthreads();
    float4 gw = ((const float4*)gate_w)[lane];
#pragma unroll
    for (int j = 0; j < 16; j++) {
        int r = (tx >> 5) + 8 * j;
        float4 hs = sx4[r * 32 + lane];
        float p = hs.x * gw.x + hs.y * gw.y + hs.z * gw.z + hs.w * gw.w;
#pragma unroll
        for (int m = 16; m; m >>= 1) p += __shfl_xor_sync(0xffffffffu, p, m);
        if (lane == 0) sge[r] = p;
    }
    __syncthreads();
    if (tx < 128) {
        float ge = __expf(sge[tx] + gate_b[0]);
        sge[tx] = ge;
        if (row0 + tx < N) atomicAdd(&g_gatesum1[sgid[tx]], ge);
    }
    __syncthreads();
#pragma unroll
    for (int j = 0; j < 16; j++) {
        int r = (tx >> 5) + 8 * j;
        int row = row0 + r;
        if (row < N) {
            float ge = sge[r];
            float4 hs = sx4[r * 32 + lane];
            red_add_v4(g_num1 + sgid[r] * 128 + lane * 4,
                       ge * hs.x, ge * hs.y, ge * hs.z, ge * hs.w);
        }
    }
    gemm_core(sx, sw, a_src, a_dst, row0, N, scale);
}

// ---------------- aggregation: warp per dst (CSR gather, fp8 rows) ----------
// R8-form inner loop; 512-thread blocks + launch_bounds to push occupancy.
__global__ void __launch_bounds__(512, 3)
k_agg(const float* __restrict__ bvec, const void* __restrict__ batch,
      int layer, int N, float invscale) {
    int n = blockIdx.x * 16 + (threadIdx.x >> 5);
    int lane = threadIdx.x & 31;
    if (n >= N) return;
    float* colsum = (layer == 1) ? g_colsum1 : g_colsum2;
    const unsigned FULL = 0xffffffffu;
    int hf = lane >> 3;
    int hq = lane & 3;
    float ald_q = g_ald[n * 4 + hq];
    float lg = g_als[n * 4 + hq] + ald_q;
    lg = lg > 0.f ? lg : 0.2f * lg;
    float wq = __expf(lg);
    float ssum_q = wq;
    float wf = __shfl_sync(FULL, wq, hf);
    float4 v = ldrow8(n, lane);
    float4 acc = make_float4(wf * v.x, wf * v.y, wf * v.z, wf * v.w);

    int beg = g_off[n], end = g_off[n + 1];
    for (int j = beg; j < end; j += 8) {
        int rem = end - j;
        int et = lane >> 2;
        int s_e = 0; float wv = 0.f;
        if (et < rem) {
            s_e = g_csr[j + et];
            float l2 = g_als[s_e * 4 + hq] + ald_q;
            l2 = l2 > 0.f ? l2 : 0.2f * l2;
            wv = __expf(l2);
        }
        ssum_q += wv;
#pragma unroll
        for (int t = 0; t < 8; t++) {
            float w = __shfl_sync(FULL, wv, t * 4 + hf);
            int s = __shfl_sync(FULL, s_e, t * 4);
            float4 u = ldrow8(s, lane);
            acc.x += w * u.x; acc.y += w * u.y; acc.z += w * u.z; acc.w += w * u.w;
        }
    }
#pragma unroll
    for (int off = 4; off < 32; off <<= 1) ssum_q += __shfl_xor_sync(FULL, ssum_q, off);
    float inv = __fdividef(invscale, __shfl_sync(FULL, ssum_q, hf));

    float4 b = ((const float4*)bvec)[lane];
    float4 u;
    u.x = fmaxf(acc.x * inv + b.x, 0.f);
    u.y = fmaxf(acc.y * inv + b.y, 0.f);
    u.z = fmaxf(acc.z * inv + b.z, 0.f);
    u.w = fmaxf(acc.w * inv + b.w, 0.f);
    float4 ev = make_float4(__expf(u.x), __expf(u.y), __expf(u.z), __expf(u.w));
    ((float4*)(g_acc + (size_t)n * 128))[lane] = ev;
    int g = load_idx(batch, n, g_idx64);
    red_add_v4(colsum + g * 128 + lane * 4, ev.x, ev.y, ev.z, ev.w);
}

// ---------------- layer-2: softmax + gate + pool ----------------
__global__ void k_ngp(const void* __restrict__ batch, const float* __restrict__ gate_w,
                      const float* __restrict__ gate_b, int N) {
    int t = blockIdx.x * blockDim.x + threadIdx.x;
    int n = t >> 5, lane = t & 31;
    if (n >= N) return;
    const unsigned FULL = 0xffffffffu;
    int g = load_idx(batch, n, g_idx64);
    float4 e = ((const float4*)(g_acc + (size_t)n * 128))[lane];
    float4 c = ((const float4*)(g_colsum2 + g * 128))[lane];
    float4 hs = make_float4(__fdividef(e.x, c.x), __fdividef(e.y, c.y),
                            __fdividef(e.z, c.z), __fdividef(e.w, c.w));
    float4 gw = ((const float4*)gate_w)[lane];
    float p = hs.x * gw.x + hs.y * gw.y + hs.z * gw.z + hs.w * gw.w;
#pragma unroll
    for (int off = 16; off; off >>= 1) p += __shfl_xor_sync(FULL, p, off);
    float ge = __expf(p + gate_b[0]);
    red_add_v4(g_num2 + g * 128 + lane * 4, ge * hs.x, ge * hs.y, ge * hs.z, ge * hs.w);
    if (lane == 0) atomicAdd(&g_gatesum2[g], ge);
}

// ---------------- MLP head (combines both layers' pooled vectors) ----------
__global__ void k_head(const float* __restrict__ lin_w, const float* __restrict__ lin_b,
                       const float* __restrict__ cls_w, const float* __restrict__ cls_b,
                       float* __restrict__ out) {
    int g = blockIdx.x;
    int j = threadIdx.x;
    __shared__ float shg[FDIM];
    __shared__ float sh[HID2];
    float inv1 = __fdividef(1.f, g_gatesum1[g]);
    float inv2 = __fdividef(1.f, g_gatesum2[g]);
#pragma unroll
    for (int r = 0; r < 2; r++) {
        int k = j + r * HID2;
        shg[k] = g_num1[g * 128 + k] * inv1 + g_num2[g * 128 + k] * inv2;
    }
    __syncthreads();
    float a = lin_b[j];
#pragma unroll 4
    for (int k = 0; k < 128; k++) a += shg[k] * lin_w[k * HID2 + j];
    sh[j] = fmaxf(a, 0.f);
    __syncthreads();
    if (j < OUTD) {
        float o = cls_b[j];
#pragma unroll
        for (int k = 0; k < HID2; k++) o += sh[k] * cls_w[k * OUTD + j];
        out[g * OUTD + j] = o;
    }
}

// ---------------- launch ----------------
extern "C" void kernel_launch(void* const* d_in, const int* in_sizes, int n_in,
                              void* d_out, int out_size) {
    const float* x      = (const float*)d_in[0];
    const void*  ei     = d_in[1];
    const void*  batch  = d_in[2];
    const float* W1     = (const float*)d_in[3];
    const float* as1    = (const float*)d_in[4];
    const float* ad1    = (const float*)d_in[5];
    const float* b1     = (const float*)d_in[6];
    const float* W2     = (const float*)d_in[7];
    const float* as2    = (const float*)d_in[8];
    const float* ad2    = (const float*)d_in[9];
    const float* b2     = (const float*)d_in[10];
    const float* gate_w = (const float*)d_in[11];
    const float* gate_b = (const float*)d_in[12];
    const float* lin_w  = (const float*)d_in[13];
    const float* lin_b  = (const float*)d_in[14];
    const float* cls_w  = (const float*)d_in[15];
    const float* cls_b  = (const float*)d_in[16];
    float* out = (float*)d_out;

    int N = in_sizes[0] / FDIM;
    long long E = (long long)in_sizes[1] / 2;

    int aggBlocks = (N + 15) / 16;
    int nodeBlocks = (N + 7) / 8;
    int edgeBlocks = (int)((E + 255) / 256);
    int scanBlocks = (N + 1023) / 1024;
    int gemmBlocks = (N + 127) / 128;
    int zgrid = (N > GNUM * FDIM ? N : GNUM * FDIM);

    size_t gemm_smem = 32768 * sizeof(float);
    size_t ngpg_smem = (32768 + 256) * sizeof(float);

    static cudaStream_t s1 = nullptr;
    static cudaEvent_t evFork = nullptr, evJoin = nullptr;
    if (!s1) {
        cudaStreamCreateWithFlags(&s1, cudaStreamNonBlocking);
        cudaEventCreateWithFlags(&evFork, cudaEventDisableTiming);
        cudaEventCreateWithFlags(&evJoin, cudaEventDisableTiming);
        cudaFuncSetAttribute(k_gemm, cudaFuncAttributeMaxDynamicSharedMemorySize, (int)gemm_smem);
        cudaFuncSetAttribute(k_ngp_gemm, cudaFuncAttributeMaxDynamicSharedMemorySize, (int)ngpg_smem);
    }

    // fork: layer-1 GEMM on s1, CSR build on main stream
    cudaEventRecord(evFork, 0);
    cudaStreamWaitEvent(s1, evFork, 0);
    k_gemm<<<gemmBlocks, 256, gemm_smem, s1>>>(x, W1, as1, ad1, N, 1.0f);
    cudaEventRecord(evJoin, s1);

    k_zero_pre<<<(zgrid + 255) / 256, 256>>>(ei, N);
    k_prep<<<edgeBlocks, 256>>>(ei, E);
    k_scan1<<<scanBlocks, 1024>>>(N);
    k_scan3<<<scanBlocks, 1024>>>(scanBlocks, N);
    k_fill<<<edgeBlocks, 256>>>(E);

    // join: agg needs CSR (main) + GEMM (s1)
    cudaStreamWaitEvent(0, evJoin, 0);

    // ---- layer 1 (fp8 rows, scale 1) ----
    k_agg<<<aggBlocks, 512>>>(b1, batch, 1, N, 1.0f);
    k_ngp_gemm<<<gemmBlocks, 256, ngpg_smem>>>(batch, gate_w, gate_b, W2, as2, ad2, N, 64.0f);

    // ---- layer 2 ----
    k_agg<<<aggBlocks, 512>>>(b2, batch, 2, N, 1.0f / 64.0f);
    k_ngp<<<nodeBlocks, 256>>>(batch, gate_w, gate_b, N);

    // head (combines both layers)
    k_head<<<GNUM, HID2>>>(lin_w, lin_b, cls_w, cls_b, out);
}

// round 17
// speedup vs baseline: 1.1024x; 1.1024x over previous
#include <cuda_runtime.h>
#include <cuda_fp16.h>
#include <cuda_fp8.h>
#include <cstdint>
#include <cstddef>

#define NMAX 50048
#define EMAX 1700000
#define FDIM 128
#define GNUM 64
#define HID2 64
#define OUTD 10

// ---------------- scratch ----------------
__device__ __align__(16) unsigned char  g_hw8 [NMAX * FDIM];
__device__ __align__(16) float g_acc[NMAX * FDIM];
__device__ __align__(16) float g_als[NMAX * 4];
__device__ __align__(16) float g_ald[NMAX * 4];
__device__ __align__(16) float g_colsum1[GNUM * FDIM];
__device__ __align__(16) float g_colsum2[GNUM * FDIM];
__device__ __align__(16) float g_num1[GNUM * FDIM];
__device__ __align__(16) float g_num2[GNUM * FDIM];
__device__ __align__(16) float g_gatesum1[GNUM];
__device__ __align__(16) float g_gatesum2[GNUM];
__device__ int g_src32[EMAX];
__device__ int g_dst32[EMAX];
__device__ int g_deg[NMAX];
__device__ int g_off[NMAX + 1];
__device__ int g_cur[NMAX];
__device__ int g_csr[EMAX];
__device__ int g_bsum[64];
__device__ int g_idx64;

__device__ __forceinline__ int load_idx(const void* p, long long i, int f64) {
    return f64 ? (int)((const long long*)p)[i] : ((const int*)p)[i];
}
__device__ __forceinline__ void red_add_v4(float* ptr, float a, float b, float c, float d) {
    asm volatile("red.global.add.v4.f32 [%0], {%1,%2,%3,%4};"
                 :: "l"(ptr), "f"(a), "f"(b), "f"(c), "f"(d) : "memory");
}
__device__ __forceinline__ void red_add_f32(float* ptr, float v) {
    asm volatile("red.global.add.f32 [%0], %1;" :: "l"(ptr), "f"(v) : "memory");
}
// fp8 row loader: lane covers features [4*lane, 4*lane+4)
__device__ __forceinline__ float4 ldrow8(int n, int lane) {
    unsigned int raw = ((const unsigned int*)(g_hw8 + (size_t)n * 128))[lane];
    __nv_fp8x2_storage_t lo = (__nv_fp8x2_storage_t)(raw & 0xffffu);
    __nv_fp8x2_storage_t hi = (__nv_fp8x2_storage_t)(raw >> 16);
    __half2_raw h0 = __nv_cvt_fp8x2_to_halfraw2(lo, __NV_E4M3);
    __half2_raw h1 = __nv_cvt_fp8x2_to_halfraw2(hi, __NV_E4M3);
    float2 f0 = __half22float2(*reinterpret_cast<__half2*>(&h0));
    float2 f1 = __half22float2(*reinterpret_cast<__half2*>(&h1));
    return make_float4(f0.x, f0.y, f1.x, f1.y);
}

// zero + index-width probe (merged)
__global__ void k_zero_pre(const void* ei, int N) {
    int t = blockIdx.x * blockDim.x + threadIdx.x;
    if (t == 0) {
        const int* w = (const int*)ei;
        int f = 1;
        for (int i = 0; i < 64; i++) if (w[2 * i + 1] != 0) { f = 0; break; }
        g_idx64 = f;
    }
    if (t < N) g_deg[t] = 0;
    if (t < GNUM * FDIM) {
        g_colsum1[t] = 0.f; g_colsum2[t] = 0.f;
        g_num1[t] = 0.f;    g_num2[t] = 0.f;
    }
    if (t < GNUM) { g_gatesum1[t] = 0.f; g_gatesum2[t] = 0.f; }
}

__global__ void k_prep(const void* __restrict__ ei, long long E) {
    long long t = (long long)blockIdx.x * blockDim.x + threadIdx.x;
    if (t >= E) return;
    int f64 = g_idx64;
    int s = load_idx(ei, t, f64);
    int d = load_idx(ei, E + t, f64);
    g_src32[t] = s;
    g_dst32[t] = d;
    atomicAdd(&g_deg[d], 1);
}

// ---- multi-block exclusive scan ----
__global__ void k_scan1(int N) {
    __shared__ int wsum[32];
    int b = blockIdx.x;
    int i = b * 1024 + threadIdx.x;
    int lane = threadIdx.x & 31, w = threadIdx.x >> 5;
    int v = (i < N) ? g_deg[i] : 0;
    int x = v;
#pragma unroll
    for (int off = 1; off < 32; off <<= 1) {
        int y = __shfl_up_sync(0xffffffffu, x, off);
        if (lane >= off) x += y;
    }
    if (lane == 31) wsum[w] = x;
    __syncthreads();
    if (w == 0) {
        int s = wsum[lane];
#pragma unroll
        for (int off = 1; off < 32; off <<= 1) {
            int y = __shfl_up_sync(0xffffffffu, s, off);
            if (lane >= off) s += y;
        }
        wsum[lane] = s;
    }
    __syncthreads();
    int excl = x - v + (w ? wsum[w - 1] : 0);
    if (i < N) g_off[i] = excl;
    if (threadIdx.x == 1023) g_bsum[b] = excl + v;
}

__global__ void k_scan3(int nb, int N) {
    __shared__ int s_off, s_tot;
    if (threadIdx.x < 32) {
        int lane = threadIdx.x;
        int v0 = (lane < nb) ? g_bsum[lane] : 0;
        int v1 = (lane + 32 < nb) ? g_bsum[lane + 32] : 0;
        int pre = 0, tot = 0;
        for (int j = 0; j < 64; j++) {
            int vj = __shfl_sync(0xffffffffu, (j < 32) ? v0 : v1, j & 31);
            if (j < (int)blockIdx.x) pre += vj;
            tot += vj;
        }
        if (lane == 0) { s_off = pre; s_tot = tot; }
    }
    __syncthreads();
    int i = blockIdx.x * 1024 + threadIdx.x;
    if (i < N) {
        int o = g_off[i] + s_off;
        g_off[i] = o;
        g_cur[i] = o;
    }
    if (blockIdx.x == 0 && threadIdx.x == 0) g_off[N] = s_tot;
}

__global__ void k_fill(long long E) {
    long long t = (long long)blockIdx.x * blockDim.x + threadIdx.x;
    if (t >= E) return;
    int s = g_src32[t];
    int d = g_dst32[t];
    int pos = atomicAdd(&g_cur[d], 1);
    g_csr[pos] = s;
}

// ---------------- register-tiled GEMM core ----------------
__device__ __forceinline__ void gemm_core(const float* sx, const float* sw,
                                          const float* __restrict__ a_src,
                                          const float* __restrict__ a_dst,
                                          int row0, int N, float scale) {
    int tx = threadIdx.x;
    int cg = tx & 15;
    int rg = tx >> 4;
    int r0 = rg * 8;
    unsigned long long acc2[8][4];
#pragma unroll
    for (int r = 0; r < 8; r++)
#pragma unroll
        for (int j = 0; j < 4; j++) acc2[r][j] = 0ull;

    for (int k = 0; k < 128; k += 4) {
        unsigned long long w0[4], w1[4], w2[4], w3[4];
#pragma unroll
        for (int j = 0; j < 4; j++) {
            w0[j] = *(const unsigned long long*)&sw[(k + 0) * 128 + j * 32 + cg * 2];
            w1[j] = *(const unsigned long long*)&sw[(k + 1) * 128 + j * 32 + cg * 2];
            w2[j] = *(const unsigned long long*)&sw[(k + 2) * 128 + j * 32 + cg * 2];
            w3[j] = *(const unsigned long long*)&sw[(k + 3) * 128 + j * 32 + cg * 2];
        }
#pragma unroll
        for (int r = 0; r < 8; r++) {
            float4 a = *(const float4*)&sx[(r0 + r) * 128 + k];
            unsigned long long da0, da1, da2, da3;
            asm("mov.b64 %0,{%1,%1};" : "=l"(da0) : "f"(a.x));
            asm("mov.b64 %0,{%1,%1};" : "=l"(da1) : "f"(a.y));
            asm("mov.b64 %0,{%1,%1};" : "=l"(da2) : "f"(a.z));
            asm("mov.b64 %0,{%1,%1};" : "=l"(da3) : "f"(a.w));
#pragma unroll
            for (int j = 0; j < 4; j++) {
                asm("fma.rn.f32x2 %0,%1,%2,%0;" : "+l"(acc2[r][j]) : "l"(da0), "l"(w0[j]));
                asm("fma.rn.f32x2 %0,%1,%2,%0;" : "+l"(acc2[r][j]) : "l"(da1), "l"(w1[j]));
                asm("fma.rn.f32x2 %0,%1,%2,%0;" : "+l"(acc2[r][j]) : "l"(da2), "l"(w2[j]));
                asm("fma.rn.f32x2 %0,%1,%2,%0;" : "+l"(acc2[r][j]) : "l"(da3), "l"(w3[j]));
            }
        }
    }
    float as_[8], ad_[8];
#pragma unroll
    for (int j = 0; j < 4; j++) {
        float2 s2 = *(const float2*)&a_src[j * 32 + cg * 2];
        float2 d2 = *(const float2*)&a_dst[j * 32 + cg * 2];
        as_[2 * j] = s2.x; as_[2 * j + 1] = s2.y;
        ad_[2 * j] = d2.x; ad_[2 * j + 1] = d2.y;
    }
#pragma unroll
    for (int r = 0; r < 8; r++) {
        int row = row0 + r0 + r;
        float e[8];
#pragma unroll
        for (int j = 0; j < 4; j++) {
            float lo, hi;
            asm("mov.b64 {%0,%1},%2;" : "=f"(lo), "=f"(hi) : "l"(acc2[r][j]));
            e[2 * j] = lo; e[2 * j + 1] = hi;
        }
        float ps[4], pd[4];
#pragma unroll
        for (int j = 0; j < 4; j++) {
            ps[j] = e[2 * j] * as_[2 * j] + e[2 * j + 1] * as_[2 * j + 1];
            pd[j] = e[2 * j] * ad_[2 * j] + e[2 * j + 1] * ad_[2 * j + 1];
        }
#pragma unroll
        for (int m = 1; m < 16; m <<= 1) {
#pragma unroll
            for (int j = 0; j < 4; j++) {
                ps[j] += __shfl_xor_sync(0xffffffffu, ps[j], m);
                pd[j] += __shfl_xor_sync(0xffffffffu, pd[j], m);
            }
        }
        if (row < N) {
#pragma unroll
            for (int j = 0; j < 4; j++) {
                unsigned short b0 = __nv_cvt_float_to_fp8(e[2 * j] * scale, __NV_SATFINITE, __NV_E4M3);
                unsigned short b1 = __nv_cvt_float_to_fp8(e[2 * j + 1] * scale, __NV_SATFINITE, __NV_E4M3);
                *(unsigned short*)&g_hw8[(size_t)row * 128 + j * 32 + cg * 2] =
                    (unsigned short)(b0 | (b1 << 8));
            }
            if (cg == 0) {
                *(float4*)&g_als[row * 4] = make_float4(ps[0], ps[1], ps[2], ps[3]);
                *(float4*)&g_ald[row * 4] = make_float4(pd[0], pd[1], pd[2], pd[3]);
            }
        }
    }
}

// ---------------- layer-1 GEMM (input x) ----------------
__global__ void __launch_bounds__(256, 1)
k_gemm(const float* __restrict__ A, const float* __restrict__ W,
       const float* __restrict__ a_src, const float* __restrict__ a_dst,
       int N, float scale) {
    extern __shared__ float smem[];
    float* sx = smem;
    float* sw = smem + 16384;
    int tx = threadIdx.x;
    int row0 = blockIdx.x * 128;
    float4* sx4 = (float4*)sx;
    float4* sw4 = (float4*)sw;
    const float4* A4 = (const float4*)A;
    const float4* W4 = (const float4*)W;
#pragma unroll
    for (int i = tx; i < 4096; i += 256) {
        int r = i >> 5;
        sx4[i] = (row0 + r < N) ? A4[(size_t)(row0 + r) * 32 + (i & 31)]
                                : make_float4(0.f, 0.f, 0.f, 0.f);
        sw4[i] = W4[i];
    }
    __syncthreads();
    gemm_core(sx, sw, a_src, a_dst, row0, N, scale);
}

// ---------------- fused: layer-1 ngp + layer-2 GEMM (staged reduction) -------
__global__ void __launch_bounds__(256, 1)
k_ngp_gemm(const void* __restrict__ batch, const float* __restrict__ gate_w,
           const float* __restrict__ gate_b, const float* __restrict__ W,
           const float* __restrict__ a_src, const float* __restrict__ a_dst,
           int N, float scale) {
    extern __shared__ float smem[];
    float* sx = smem;
    float* sw = smem + 16384;
    float* sge = smem + 32768;            // 128
    int* sgid = (int*)(smem + 32896);     // 128
    float* slots = smem + 33024;          // 4*128
    float* sgate = smem + 33536;          // 4
    int tx = threadIdx.x;
    int lane = tx & 31;
    int row0 = blockIdx.x * 128;
    int f64 = g_idx64;
    float4* sx4 = (float4*)sx;
    float4* sw4 = (float4*)sw;
    const float4* W4 = (const float4*)W;
    const float4* acc4 = (const float4*)g_acc;
    for (int i = tx; i < 512; i += 256) slots[i] = 0.f;
    if (tx < 4) sgate[tx] = 0.f;
#pragma unroll
    for (int i = tx; i < 4096; i += 256) {
        int r = i >> 5, c = i & 31;
        int row = row0 + r;
        if (row < N) {
            int g = load_idx(batch, row, f64);
            if (c == 0) sgid[r] = g;
            float4 e = acc4[(size_t)row * 32 + c];
            float4 cs = ((const float4*)(g_colsum1 + g * 128))[c];
            sx4[i] = make_float4(__fdividef(e.x, cs.x), __fdividef(e.y, cs.y),
                                 __fdividef(e.z, cs.z), __fdividef(e.w, cs.w));
        } else {
            if (c == 0) sgid[r] = 0;
            sx4[i] = make_float4(0.f, 0.f, 0.f, 0.f);
        }
        sw4[i] = W4[i];
    }
    __syncthreads();
    int gfirst = sgid[0];
    float4 gw = ((const float4*)gate_w)[lane];
#pragma unroll
    for (int j = 0; j < 16; j++) {
        int r = (tx >> 5) + 8 * j;
        float4 hs = sx4[r * 32 + lane];
        float p = hs.x * gw.x + hs.y * gw.y + hs.z * gw.z + hs.w * gw.w;
#pragma unroll
        for (int m = 16; m; m >>= 1) p += __shfl_xor_sync(0xffffffffu, p, m);
        if (lane == 0) sge[r] = p;
    }
    __syncthreads();
    if (tx < 128) {
        float ge = __expf(sge[tx] + gate_b[0]);
        sge[tx] = ge;
        if (row0 + tx < N) {
            int slot = sgid[tx] - gfirst;
            if (slot < 4) atomicAdd(&sgate[slot], ge);
            else atomicAdd(&g_gatesum1[sgid[tx]], ge);
        }
    }
    __syncthreads();
#pragma unroll
    for (int j = 0; j < 16; j++) {
        int r = (tx >> 5) + 8 * j;
        int row = row0 + r;
        if (row < N) {
            float ge = sge[r];
            float4 hs = sx4[r * 32 + lane];
            int slot = sgid[r] - gfirst;
            if (slot < 4) {
                atomicAdd(&slots[slot * 128 + lane * 4 + 0], ge * hs.x);
                atomicAdd(&slots[slot * 128 + lane * 4 + 1], ge * hs.y);
                atomicAdd(&slots[slot * 128 + lane * 4 + 2], ge * hs.z);
                atomicAdd(&slots[slot * 128 + lane * 4 + 3], ge * hs.w);
            } else {
                red_add_v4(g_num1 + sgid[r] * 128 + lane * 4,
                           ge * hs.x, ge * hs.y, ge * hs.z, ge * hs.w);
            }
        }
    }
    __syncthreads();
    for (int i = tx; i < 512; i += 256) {
        float v = slots[i];
        if (v != 0.f) red_add_f32(g_num1 + (gfirst + (i >> 7)) * 128 + (i & 127), v);
    }
    if (tx < 4 && sgate[tx] != 0.f) red_add_f32(&g_gatesum1[gfirst + tx], sgate[tx]);
    gemm_core(sx, sw, a_src, a_dst, row0, N, scale);
}

// ---------------- aggregation: warp per dst (staged colsum reduction) --------
__global__ void __launch_bounds__(256)
k_agg(const float* __restrict__ bvec, const void* __restrict__ batch,
      int layer, int N, float invscale) {
    __shared__ float slots[4][128];
    __shared__ int sgfirst;
    float* colsum = (layer == 1) ? g_colsum1 : g_colsum2;
    int tid = threadIdx.x;
    int lane = tid & 31;
    ((float*)slots)[tid] = 0.f;
    ((float*)slots)[tid + 256] = 0.f;
    int f64 = g_idx64;
    if (tid == 0) {
        int n0 = blockIdx.x * 8;
        if (n0 >= N) n0 = N - 1;
        sgfirst = load_idx(batch, n0, f64);
    }
    __syncthreads();
    int n = blockIdx.x * 8 + (tid >> 5);
    bool active = (n < N);
    const unsigned FULL = 0xffffffffu;
    float4 ev = make_float4(0.f, 0.f, 0.f, 0.f);
    int g = 0;
    if (active) {
        int hf = lane >> 3;
        int hq = lane & 3;
        float ald_q = g_ald[n * 4 + hq];
        float lg = g_als[n * 4 + hq] + ald_q;
        lg = lg > 0.f ? lg : 0.2f * lg;
        float wq = __expf(lg);
        float ssum_q = wq;
        float wf = __shfl_sync(FULL, wq, hf);
        float4 v = ldrow8(n, lane);
        float4 acc = make_float4(wf * v.x, wf * v.y, wf * v.z, wf * v.w);

        int beg = g_off[n], end = g_off[n + 1];
        for (int j = beg; j < end; j += 8) {
            int rem = end - j;
            int et = lane >> 2;
            int s_e = 0; float wv = 0.f;
            if (et < rem) {
                s_e = g_csr[j + et];
                float l2 = g_als[s_e * 4 + hq] + ald_q;
                l2 = l2 > 0.f ? l2 : 0.2f * l2;
                wv = __expf(l2);
            }
            ssum_q += wv;
#pragma unroll
            for (int t = 0; t < 8; t++) {
                float w = __shfl_sync(FULL, wv, t * 4 + hf);
                int s = __shfl_sync(FULL, s_e, t * 4);
                float4 u = ldrow8(s, lane);
                acc.x += w * u.x; acc.y += w * u.y; acc.z += w * u.z; acc.w += w * u.w;
            }
        }
#pragma unroll
        for (int off = 4; off < 32; off <<= 1) ssum_q += __shfl_xor_sync(FULL, ssum_q, off);
        float inv = __fdividef(invscale, __shfl_sync(FULL, ssum_q, hf));

        float4 b = ((const float4*)bvec)[lane];
        float4 u;
        u.x = fmaxf(acc.x * inv + b.x, 0.f);
        u.y = fmaxf(acc.y * inv + b.y, 0.f);
        u.z = fmaxf(acc.z * inv + b.z, 0.f);
        u.w = fmaxf(acc.w * inv + b.w, 0.f);
        ev = make_float4(__expf(u.x), __expf(u.y), __expf(u.z), __expf(u.w));
        ((float4*)(g_acc + (size_t)n * 128))[lane] = ev;
        g = load_idx(batch, n, f64);
        int slot = g - sgfirst;
        if (slot < 4) {
            atomicAdd(&slots[slot][lane * 4 + 0], ev.x);
            atomicAdd(&slots[slot][lane * 4 + 1], ev.y);
            atomicAdd(&slots[slot][lane * 4 + 2], ev.z);
            atomicAdd(&slots[slot][lane * 4 + 3], ev.w);
        } else {
            red_add_v4(colsum + g * 128 + lane * 4, ev.x, ev.y, ev.z, ev.w);
        }
    }
    __syncthreads();
#pragma unroll
    for (int i = tid; i < 512; i += 256) {
        float v = ((float*)slots)[i];
        if (v != 0.f) red_add_f32(colsum + (sgfirst + (i >> 7)) * 128 + (i & 127), v);
    }
}

// ---------------- layer-2: softmax + gate + pool (staged reduction) ----------
__global__ void __launch_bounds__(256)
k_ngp(const void* __restrict__ batch, const float* __restrict__ gate_w,
      const float* __restrict__ gate_b, int N) {
    __shared__ float slots[4][128];
    __shared__ float sgate[4];
    __shared__ int sgfirst;
    int tid = threadIdx.x;
    int lane = tid & 31;
    ((float*)slots)[tid] = 0.f;
    ((float*)slots)[tid + 256] = 0.f;
    if (tid < 4) sgate[tid] = 0.f;
    int f64 = g_idx64;
    if (tid == 0) {
        int n0 = blockIdx.x * 8;
        if (n0 >= N) n0 = N - 1;
        sgfirst = load_idx(batch, n0, f64);
    }
    __syncthreads();
    int n = blockIdx.x * 8 + (tid >> 5);
    const unsigned FULL = 0xffffffffu;
    if (n < N) {
        int g = load_idx(batch, n, f64);
        float4 e = ((const float4*)(g_acc + (size_t)n * 128))[lane];
        float4 c = ((const float4*)(g_colsum2 + g * 128))[lane];
        float4 hs = make_float4(__fdividef(e.x, c.x), __fdividef(e.y, c.y),
                                __fdividef(e.z, c.z), __fdividef(e.w, c.w));
        float4 gw = ((const float4*)gate_w)[lane];
        float p = hs.x * gw.x + hs.y * gw.y + hs.z * gw.z + hs.w * gw.w;
#pragma unroll
        for (int off = 16; off; off >>= 1) p += __shfl_xor_sync(FULL, p, off);
        float ge = __expf(p + gate_b[0]);
        int slot = g - sgfirst;
        if (slot < 4) {
            atomicAdd(&slots[slot][lane * 4 + 0], ge * hs.x);
            atomicAdd(&slots[slot][lane * 4 + 1], ge * hs.y);
            atomicAdd(&slots[slot][lane * 4 + 2], ge * hs.z);
            atomicAdd(&slots[slot][lane * 4 + 3], ge * hs.w);
            if (lane == 0) atomicAdd(&sgate[slot], ge);
        } else {
            red_add_v4(g_num2 + g * 128 + lane * 4, ge * hs.x, ge * hs.y, ge * hs.z, ge * hs.w);
            if (lane == 0) atomicAdd(&g_gatesum2[g], ge);
        }
    }
    __syncthreads();
#pragma unroll
    for (int i = tid; i < 512; i += 256) {
        float v = ((float*)slots)[i];
        if (v != 0.f) red_add_f32(g_num2 + (sgfirst + (i >> 7)) * 128 + (i & 127), v);
    }
    if (tid < 4 && sgate[tid] != 0.f) red_add_f32(&g_gatesum2[sgfirst + tid], sgate[tid]);
}

// ---------------- MLP head (combines both layers' pooled vectors) ----------
__global__ void k_head(const float* __restrict__ lin_w, const float* __restrict__ lin_b,
                       const float* __restrict__ cls_w, const float* __restrict__ cls_b,
                       float* __restrict__ out) {
    int g = blockIdx.x;
    int j = threadIdx.x;
    __shared__ float shg[FDIM];
    __shared__ float sh[HID2];
    float inv1 = __fdividef(1.f, g_gatesum1[g]);
    float inv2 = __fdividef(1.f, g_gatesum2[g]);
#pragma unroll
    for (int r = 0; r < 2; r++) {
        int k = j + r * HID2;
        shg[k] = g_num1[g * 128 + k] * inv1 + g_num2[g * 128 + k] * inv2;
    }
    __syncthreads();
    float a = lin_b[j];
#pragma unroll 4
    for (int k = 0; k < 128; k++) a += shg[k] * lin_w[k * HID2 + j];
    sh[j] = fmaxf(a, 0.f);
    __syncthreads();
    if (j < OUTD) {
        float o = cls_b[j];
#pragma unroll
        for (int k = 0; k < HID2; k++) o += sh[k] * cls_w[k * OUTD + j];
        out[g * OUTD + j] = o;
    }
}

// ---------------- launch ----------------
extern "C" void kernel_launch(void* const* d_in, const int* in_sizes, int n_in,
                              void* d_out, int out_size) {
    const float* x      = (const float*)d_in[0];
    const void*  ei     = d_in[1];
    const void*  batch  = d_in[2];
    const float* W1     = (const float*)d_in[3];
    const float* as1    = (const float*)d_in[4];
    const float* ad1    = (const float*)d_in[5];
    const float* b1     = (const float*)d_in[6];
    const float* W2     = (const float*)d_in[7];
    const float* as2    = (const float*)d_in[8];
    const float* ad2    = (const float*)d_in[9];
    const float* b2     = (const float*)d_in[10];
    const float* gate_w = (const float*)d_in[11];
    const float* gate_b = (const float*)d_in[12];
    const float* lin_w  = (const float*)d_in[13];
    const float* lin_b  = (const float*)d_in[14];
    const float* cls_w  = (const float*)d_in[15];
    const float* cls_b  = (const float*)d_in[16];
    float* out = (float*)d_out;

    int N = in_sizes[0] / FDIM;
    long long E = (long long)in_sizes[1] / 2;

    int nodeBlocks = (N + 7) / 8;
    int edgeBlocks = (int)((E + 255) / 256);
    int scanBlocks = (N + 1023) / 1024;
    int gemmBlocks = (N + 127) / 128;
    int zgrid = (N > GNUM * FDIM ? N : GNUM * FDIM);

    size_t gemm_smem = 32768 * sizeof(float);
    size_t ngpg_smem = 33540 * sizeof(float);

    static cudaStream_t s1 = nullptr;
    static cudaEvent_t evFork = nullptr, evJoin = nullptr;
    if (!s1) {
        cudaStreamCreateWithFlags(&s1, cudaStreamNonBlocking);
        cudaEventCreateWithFlags(&evFork, cudaEventDisableTiming);
        cudaEventCreateWithFlags(&evJoin, cudaEventDisableTiming);
        cudaFuncSetAttribute(k_gemm, cudaFuncAttributeMaxDynamicSharedMemorySize, (int)gemm_smem);
        cudaFuncSetAttribute(k_ngp_gemm, cudaFuncAttributeMaxDynamicSharedMemorySize, (int)ngpg_smem);
    }

    // fork: layer-1 GEMM on s1, CSR build on main stream
    cudaEventRecord(evFork, 0);
    cudaStreamWaitEvent(s1, evFork, 0);
    k_gemm<<<gemmBlocks, 256, gemm_smem, s1>>>(x, W1, as1, ad1, N, 1.0f);
    cudaEventRecord(evJoin, s1);

    k_zero_pre<<<(zgrid + 255) / 256, 256>>>(ei, N);
    k_prep<<<edgeBlocks, 256>>>(ei, E);
    k_scan1<<<scanBlocks, 1024>>>(N);
    k_scan3<<<scanBlocks, 1024>>>(scanBlocks, N);
    k_fill<<<edgeBlocks, 256>>>(E);

    // join: agg needs CSR (main) + GEMM (s1)
    cudaStreamWaitEvent(0, evJoin, 0);

    // ---- layer 1 (fp8 rows, scale 1) ----
    k_agg<<<nodeBlocks, 256>>>(b1, batch, 1, N, 1.0f);
    k_ngp_gemm<<<gemmBlocks, 256, ngpg_smem>>>(batch, gate_w, gate_b, W2, as2, ad2, N, 64.0f);

    // ---- layer 2 ----
    k_agg<<<nodeBlocks, 256>>>(b2, batch, 2, N, 1.0f / 64.0f);
    k_ngp<<<nodeBlocks, 256>>>(batch, gate_w, gate_b, N);

    // head (combines both layers)
    k_head<<<GNUM, HID2>>>(lin_w, lin_b, cls_w, cls_b, out);
}